// round 1
// baseline (speedup 1.0000x reference)
#include <cuda_runtime.h>
#include <math.h>

#define BATCH 4096
#define FEAT  4096
#define THREADS 256

// Per-row hinged values scratch (no device allocation allowed).
__device__ float g_row_vals[BATCH];

__global__ __launch_bounds__(THREADS)
void row_dist_kernel(const float* __restrict__ o1,
                     const float* __restrict__ o2,
                     const float* __restrict__ o3) {
    const int row = blockIdx.x;
    const size_t base = (size_t)row * FEAT;
    const float4* __restrict__ a = reinterpret_cast<const float4*>(o1 + base);
    const float4* __restrict__ b = reinterpret_cast<const float4*>(o2 + base);
    const float4* __restrict__ c = reinterpret_cast<const float4*>(o3 + base);

    const int tid = threadIdx.x;
    const int nvec = FEAT / 4;            // 1024 float4 per row
    const int per_thread = nvec / THREADS; // 4

    float s13 = 0.0f;
    float s12 = 0.0f;

#pragma unroll
    for (int it = 0; it < per_thread; ++it) {
        int i = tid + it * THREADS;
        float4 x = a[i];
        float4 y = b[i];
        float4 z = c[i];

        float d;
        d = x.x - z.x; s13 = fmaf(d, d, s13);
        d = x.y - z.y; s13 = fmaf(d, d, s13);
        d = x.z - z.z; s13 = fmaf(d, d, s13);
        d = x.w - z.w; s13 = fmaf(d, d, s13);

        d = x.x - y.x; s12 = fmaf(d, d, s12);
        d = x.y - y.y; s12 = fmaf(d, d, s12);
        d = x.z - y.z; s12 = fmaf(d, d, s12);
        d = x.w - y.w; s12 = fmaf(d, d, s12);
    }

    // Warp reduce both accumulators
#pragma unroll
    for (int off = 16; off > 0; off >>= 1) {
        s13 += __shfl_down_sync(0xFFFFFFFFu, s13, off);
        s12 += __shfl_down_sync(0xFFFFFFFFu, s12, off);
    }

    __shared__ float sm13[THREADS / 32];
    __shared__ float sm12[THREADS / 32];
    const int lane = tid & 31;
    const int wid = tid >> 5;
    if (lane == 0) { sm13[wid] = s13; sm12[wid] = s12; }
    __syncthreads();

    if (wid == 0) {
        s13 = (lane < THREADS / 32) ? sm13[lane] : 0.0f;
        s12 = (lane < THREADS / 32) ? sm12[lane] : 0.0f;
#pragma unroll
        for (int off = 4; off > 0; off >>= 1) {
            s13 += __shfl_down_sync(0xFFFFFFFFu, s13, off);
            s12 += __shfl_down_sync(0xFFFFFFFFu, s12, off);
        }
        if (lane == 0) {
            float compare = 2.0f - sqrtf(s13) + sqrtf(s12);
            g_row_vals[row] = fmaxf(0.0f, compare);
        }
    }
}

__global__ __launch_bounds__(1024)
void final_reduce_kernel(float* __restrict__ out) {
    const int tid = threadIdx.x;
    float s = 0.0f;
#pragma unroll
    for (int it = 0; it < BATCH / 1024; ++it)
        s += g_row_vals[tid + it * 1024];

#pragma unroll
    for (int off = 16; off > 0; off >>= 1)
        s += __shfl_down_sync(0xFFFFFFFFu, s, off);

    __shared__ float sm[32];
    const int lane = tid & 31;
    const int wid = tid >> 5;
    if (lane == 0) sm[wid] = s;
    __syncthreads();

    if (wid == 0) {
        s = (lane < 32) ? sm[lane] : 0.0f;
#pragma unroll
        for (int off = 16; off > 0; off >>= 1)
            s += __shfl_down_sync(0xFFFFFFFFu, s, off);
        if (lane == 0)
            out[0] = s * (float)BATCH;  // broadcast-sum over [B,B]
    }
}

extern "C" void kernel_launch(void* const* d_in, const int* in_sizes, int n_in,
                              void* d_out, int out_size) {
    const float* o1 = (const float*)d_in[0];
    const float* o2 = (const float*)d_in[1];
    const float* o3 = (const float*)d_in[2];
    float* out = (float*)d_out;

    row_dist_kernel<<<BATCH, THREADS>>>(o1, o2, o3);
    final_reduce_kernel<<<1, 1024>>>(out);
}